// round 15
// baseline (speedup 1.0000x reference)
#include <cuda_runtime.h>
#include <cuda_bf16.h>
#include <cstdint>

// Problem constants
#define BB 2
#define CC 64
#define NN 9216
#define CQD 8
#define NSPLIT 3
#define KEYS_PER_SPLIT (NN / NSPLIT)            // 3072
#define KT 64                                    // keys per tile
#define TILES_PER_SPLIT (KEYS_PER_SPLIT / KT)    // 48
#define QBLK 128
#define NQT (NN / QBLK)                          // 72
#define VP 72                                    // Vs row pitch in bf16 (144 B)
#define LOG2E 1.4426950408889634f

// Scratch (device globals; no allocation allowed)
__device__ float g_Q[BB * NN * CQD];                         // tf32( q * log2e )
__device__ float g_K[BB * NN * CQD];                         // tf32, pair-PERMUTED
__device__ __align__(16) __nv_bfloat16 g_Vb[BB * NN * CC];   // bf16
__device__ __align__(16) __nv_bfloat16 g_accPh[NSPLIT * BB * NN * CC]; // partial O (bf16)
__device__ float g_lP[NSPLIT * BB * NN];                     // partial exp-sums
__device__ unsigned int g_cnt[BB * NQT];                     // split counters (0-init)

// ---------------------------------------------------------------------------
// PTX helpers
// ---------------------------------------------------------------------------
__device__ __forceinline__ uint32_t smem_u32(const void* p) {
    return (uint32_t)__cvta_generic_to_shared(p);
}

__device__ __forceinline__ void cp_async16(uint32_t dst, const void* src) {
    asm volatile("cp.async.cg.shared.global [%0], [%1], 16;" :: "r"(dst), "l"(src));
}
#define CP_COMMIT() asm volatile("cp.async.commit_group;")
#define CP_WAIT0()  asm volatile("cp.async.wait_group 0;")

__device__ __forceinline__ void ldmatrix_x4_trans(uint32_t& r0, uint32_t& r1,
                                                  uint32_t& r2, uint32_t& r3,
                                                  uint32_t addr) {
    asm volatile("ldmatrix.sync.aligned.m8n8.x4.trans.shared.b16 {%0,%1,%2,%3}, [%4];"
                 : "=r"(r0), "=r"(r1), "=r"(r2), "=r"(r3) : "r"(addr));
}

// bf16 PV mma: D(16x8) += A(16x16) * B(16x8)
__device__ __forceinline__ void mma16816(float& c0, float& c1, float& c2, float& c3,
                                         uint32_t a0, uint32_t a1, uint32_t a2, uint32_t a3,
                                         uint32_t b0, uint32_t b1) {
    asm volatile(
        "mma.sync.aligned.m16n8k16.row.col.f32.bf16.bf16.f32 "
        "{%0,%1,%2,%3}, {%4,%5,%6,%7}, {%8,%9}, {%0,%1,%2,%3};"
        : "+f"(c0), "+f"(c1), "+f"(c2), "+f"(c3)
        : "r"(a0), "r"(a1), "r"(a2), "r"(a3), "r"(b0), "r"(b1));
}

// tf32 QK mma: D(16x8) = A(16x8) * B(8x8)
__device__ __forceinline__ void mma_tf32(float& c0, float& c1, float& c2, float& c3,
                                         uint32_t a0, uint32_t a1, uint32_t a2, uint32_t a3,
                                         uint32_t b0, uint32_t b1) {
    asm volatile(
        "mma.sync.aligned.m16n8k8.row.col.f32.tf32.tf32.f32 "
        "{%0,%1,%2,%3}, {%4,%5,%6,%7}, {%8,%9}, {%0,%1,%2,%3};"
        : "+f"(c0), "+f"(c1), "+f"(c2), "+f"(c3)
        : "r"(a0), "r"(a1), "r"(a2), "r"(a3), "r"(b0), "r"(b1));
}

__device__ __forceinline__ float to_tf32(float x) {
    uint32_t y;
    asm("cvt.rna.tf32.f32 %0, %1;" : "=r"(y) : "f"(x));
    return __uint_as_float(y);
}

__device__ __forceinline__ float ex2(float x) {
    float y;
    asm("ex2.approx.f32 %0, %1;" : "=f"(y) : "f"(x));
    return y;
}

// ---------------------------------------------------------------------------
// Kernel 1: 1x1-conv projections (round-6 best-measured shape).
// grid (36, B, 4), 256 threads; z picks 20 of 80 outputs.
// K stored pair-PERMUTED: K'[2c]=K[c], K'[2c+1]=K[c+4] (c=0..3).
// ---------------------------------------------------------------------------
__global__ __launch_bounds__(256) void proj_kernel(
    const float* __restrict__ X,
    const float* __restrict__ Wq, const float* __restrict__ bq,
    const float* __restrict__ Wk, const float* __restrict__ bk,
    const float* __restrict__ Wv, const float* __restrict__ bv)
{
    __shared__ float Ws[20 * 64];
    __shared__ float bs[20];

    const int t = threadIdx.x;
    const int b = blockIdx.y;
    const int z = blockIdx.z;
    const int n = blockIdx.x * 256 + t;
    const int obase = z * 20;

    for (int i = t; i < 20 * 64; i += 256) {
        const int o = obase + (i >> 6), c = i & 63;
        Ws[i] = (o < 8) ? Wq[o * 64 + c]
              : (o < 16) ? Wk[(o - 8) * 64 + c]
                         : Wv[(o - 16) * 64 + c];
    }
    if (t < 20) {
        const int o = obase + t;
        bs[t] = (o < 8) ? bq[o] : (o < 16) ? bk[o - 8] : bv[o - 16];
    }

    float x[64];
    const float* Xb = X + (size_t)b * CC * NN + n;
#pragma unroll
    for (int c = 0; c < 64; ++c) x[c] = Xb[(size_t)c * NN];

    __syncthreads();

    float* qrow = &g_Q[(size_t)(b * NN + n) * CQD];
    float* krow = &g_K[(size_t)(b * NN + n) * CQD];
    __nv_bfloat16* vrow = &g_Vb[(size_t)(b * NN + n) * CC];

    const float4* Ws4 = (const float4*)Ws;
#pragma unroll 4
    for (int oo = 0; oo < 20; ++oo) {
        float a0 = bs[oo], a1 = 0.f, a2 = 0.f, a3 = 0.f;
#pragma unroll
        for (int c4 = 0; c4 < 16; c4 += 4) {
            const float4 w0 = Ws4[oo * 16 + c4 + 0];
            const float4 w1 = Ws4[oo * 16 + c4 + 1];
            const float4 w2 = Ws4[oo * 16 + c4 + 2];
            const float4 w3 = Ws4[oo * 16 + c4 + 3];
            a0 = fmaf(w0.x, x[4*c4+0],  a0); a0 = fmaf(w0.y, x[4*c4+1],  a0);
            a0 = fmaf(w0.z, x[4*c4+2],  a0); a0 = fmaf(w0.w, x[4*c4+3],  a0);
            a1 = fmaf(w1.x, x[4*c4+4],  a1); a1 = fmaf(w1.y, x[4*c4+5],  a1);
            a1 = fmaf(w1.z, x[4*c4+6],  a1); a1 = fmaf(w1.w, x[4*c4+7],  a1);
            a2 = fmaf(w2.x, x[4*c4+8],  a2); a2 = fmaf(w2.y, x[4*c4+9],  a2);
            a2 = fmaf(w2.z, x[4*c4+10], a2); a2 = fmaf(w2.w, x[4*c4+11], a2);
            a3 = fmaf(w3.x, x[4*c4+12], a3); a3 = fmaf(w3.y, x[4*c4+13], a3);
            a3 = fmaf(w3.z, x[4*c4+14], a3); a3 = fmaf(w3.w, x[4*c4+15], a3);
        }
        const float acc = (a0 + a1) + (a2 + a3);
        const int o = obase + oo;
        if (o < 8) {
            qrow[o] = to_tf32(acc * LOG2E);
        } else if (o < 16) {
            const int c = o - 8;
            const int idx = (c < 4) ? 2 * c : 2 * (c - 4) + 1;   // pair permutation
            krow[idx] = to_tf32(acc);
        } else {
            vrow[o - 16] = __float2bfloat16(acc);
        }
    }
}

// ---------------------------------------------------------------------------
// Kernel 2: partial attention + fused combine, software-pipelined chunks.
// grid (72, B, NSPLIT=3); 256 threads = 8 warps; warp owns 16 query rows.
// vs round 14: l accumulated with FADD (off the tensor pipe: 8 HMMA/chunk
// instead of 9), and the PV ldmatrix stream runs one step ahead of its
// consuming mma pair (LDS latency hidden by ~2 mma of distance).
// ---------------------------------------------------------------------------
__global__ __launch_bounds__(256, 3) void attn_partial(
    const float* __restrict__ X,
    const float* __restrict__ gamma_p,
    float* __restrict__ out)
{
    __shared__ float Ks[2][KT * 8];                  // 2 x 2 KB
    __shared__ __nv_bfloat16 Vs[2][KT * VP];         // 2 x 9 KB
    __shared__ unsigned int s_last;

    const int t    = threadIdx.x;
    const int lane = t & 31;
    const int w    = t >> 5;
    const int b    = blockIdx.y;
    const int s    = blockIdx.z;
    const int qt   = blockIdx.x;
    const int g    = lane >> 2;
    const int tig  = lane & 3;

    // Q fragment (loop-invariant)
    const float* Qb = &g_Q[(size_t)(b * NN + qt * QBLK + w * 16) * CQD];
    const uint32_t qa0 = __float_as_uint(Qb[g * CQD + tig]);
    const uint32_t qa1 = __float_as_uint(Qb[(g + 8) * CQD + tig]);
    const uint32_t qa2 = __float_as_uint(Qb[g * CQD + tig + 4]);
    const uint32_t qa3 = __float_as_uint(Qb[(g + 8) * CQD + tig + 4]);

    float C[8][4];
#pragma unroll
    for (int i = 0; i < 8; ++i)
#pragma unroll
        for (int j = 0; j < 4; ++j) C[i][j] = 0.f;
    float l0 = 0.f, l8 = 0.f;

    const int kbase0 = s * KEYS_PER_SPLIT;
    const int vrow0  = t >> 3;            // 0..31
    const int vch    = (t & 7) * 8;       // bf16 col 0..56

    const uint32_t ks_u32[2] = { smem_u32(Ks[0]), smem_u32(Ks[1]) };
    const uint32_t vs_u32[2] = { smem_u32(Vs[0]), smem_u32(Vs[1]) };
    const uint32_t b_off = (lane & 15) * (VP * 2) + (lane >> 4) * 16;
    const uint32_t k_off = (uint32_t)(g * 32 + tig * 8);   // packed-pair byte offset

#define STAGE(TILE, BUF)                                                             \
    do {                                                                             \
        const size_t kb_ = (size_t)(b * NN + kbase0 + (TILE) * KT);                  \
        if (t < 128)                                                                 \
            cp_async16(ks_u32[BUF] + t * 16, (const char*)&g_K[kb_ * CQD] + t * 16); \
        cp_async16(vs_u32[BUF] + (vrow0 * VP + vch) * 2,                             \
                   &g_Vb[(kb_ + vrow0) * CC + vch]);                                 \
        cp_async16(vs_u32[BUF] + ((vrow0 + 32) * VP + vch) * 2,                      \
                   &g_Vb[(kb_ + vrow0 + 32) * CC + vch]);                            \
    } while (0)

    // QK (2 packed LDS.64 + 2 tf32 mma) for a 16-key chunk
#define QK_MMA(KSBASE, CT2, CN)                                                      \
    do {                                                                             \
        uint32_t kb0_, kb1_, kb2_, kb3_;                                             \
        asm volatile("ld.shared.v2.b32 {%0,%1}, [%2];"                               \
                     : "=r"(kb0_), "=r"(kb1_) : "r"((KSBASE) + (CT2) * 256));        \
        asm volatile("ld.shared.v2.b32 {%0,%1}, [%2];"                               \
                     : "=r"(kb2_), "=r"(kb3_) : "r"((KSBASE) + (CT2) * 256 + 256));  \
        (CN)[0] = 0.f; (CN)[1] = 0.f; (CN)[2] = 0.f; (CN)[3] = 0.f;                  \
        (CN)[4] = 0.f; (CN)[5] = 0.f; (CN)[6] = 0.f; (CN)[7] = 0.f;                  \
        mma_tf32((CN)[0], (CN)[1], (CN)[2], (CN)[3], qa0, qa1, qa2, qa3, kb0_, kb1_);\
        mma_tf32((CN)[4], (CN)[5], (CN)[6], (CN)[7], qa0, qa1, qa2, qa3, kb2_, kb3_);\
    } while (0)

    // EX2 + FADD l-accum + pack 8 logits into 4 A-frag words
    // cn[0],cn[1],cn[4],cn[5] are rows g (l0); cn[2],cn[3],cn[6],cn[7] rows g+8 (l8)
#define EXP_PACK(CN, A)                                                              \
    do {                                                                             \
        const float e0_ = ex2((CN)[0]), e1_ = ex2((CN)[1]);                          \
        const float e2_ = ex2((CN)[2]), e3_ = ex2((CN)[3]);                          \
        const float e4_ = ex2((CN)[4]), e5_ = ex2((CN)[5]);                          \
        const float e6_ = ex2((CN)[6]), e7_ = ex2((CN)[7]);                          \
        l0 += (e0_ + e1_) + (e4_ + e5_);                                             \
        l8 += (e2_ + e3_) + (e6_ + e7_);                                             \
        const __nv_bfloat162 p01_ = __floats2bfloat162_rn(e0_, e1_);                 \
        const __nv_bfloat162 p23_ = __floats2bfloat162_rn(e2_, e3_);                 \
        const __nv_bfloat162 p45_ = __floats2bfloat162_rn(e4_, e5_);                 \
        const __nv_bfloat162 p67_ = __floats2bfloat162_rn(e6_, e7_);                 \
        (A)[0] = *(const uint32_t*)&p01_;                                            \
        (A)[1] = *(const uint32_t*)&p23_;                                            \
        (A)[2] = *(const uint32_t*)&p45_;                                            \
        (A)[3] = *(const uint32_t*)&p67_;                                            \
    } while (0)

    // PV for one chunk: ldmatrix stream one step ahead of consuming mma pairs
#define PV_MMA(BBASE, KC, A)                                                         \
    do {                                                                             \
        const uint32_t pb_ = (BBASE) + (KC) * 16 * (VP * 2);                         \
        uint32_t b0_, b1_, b2_, b3_, c0_, c1_, c2_, c3_;                             \
        ldmatrix_x4_trans(b0_, b1_, b2_, b3_, pb_);                                  \
        ldmatrix_x4_trans(c0_, c1_, c2_, c3_, pb_ + 32);                             \
        mma16816(C[0][0], C[0][1], C[0][2], C[0][3],                                 \
                 (A)[0], (A)[1], (A)[2], (A)[3], b0_, b1_);                          \
        mma16816(C[1][0], C[1][1], C[1][2], C[1][3],                                 \
                 (A)[0], (A)[1], (A)[2], (A)[3], b2_, b3_);                          \
        ldmatrix_x4_trans(b0_, b1_, b2_, b3_, pb_ + 64);                             \
        mma16816(C[2][0], C[2][1], C[2][2], C[2][3],                                 \
                 (A)[0], (A)[1], (A)[2], (A)[3], c0_, c1_);                          \
        mma16816(C[3][0], C[3][1], C[3][2], C[3][3],                                 \
                 (A)[0], (A)[1], (A)[2], (A)[3], c2_, c3_);                          \
        ldmatrix_x4_trans(c0_, c1_, c2_, c3_, pb_ + 96);                             \
        mma16816(C[4][0], C[4][1], C[4][2], C[4][3],                                 \
                 (A)[0], (A)[1], (A)[2], (A)[3], b0_, b1_);                          \
        mma16816(C[5][0], C[5][1], C[5][2], C[5][3],                                 \
                 (A)[0], (A)[1], (A)[2], (A)[3], b2_, b3_);                          \
        mma16816(C[6][0], C[6][1], C[6][2], C[6][3],                                 \
                 (A)[0], (A)[1], (A)[2], (A)[3], c0_, c1_);                          \
        mma16816(C[7][0], C[7][1], C[7][2], C[7][3],                                 \
                 (A)[0], (A)[1], (A)[2], (A)[3], c2_, c3_);                          \
    } while (0)

    STAGE(0, 0);
    CP_COMMIT();

    for (int tile = 0; tile < TILES_PER_SPLIT; ++tile) {
        const int cur = tile & 1;

        CP_WAIT0();
        __syncthreads();          // buffer cur ready for all warps

        if (tile + 1 < TILES_PER_SPLIT) {
            STAGE(tile + 1, cur ^ 1);
            CP_COMMIT();
        }

        const uint32_t ks_base = ks_u32[cur] + k_off;
        const uint32_t b_base  = vs_u32[cur] + b_off;

        // pipeline prologue: A-frags for chunk 0
        float cn[8];
        uint32_t A[4];
        QK_MMA(ks_base, 0, cn);
        EXP_PACK(cn, A);

#pragma unroll
        for (int kc = 0; kc < 4; ++kc) {
            // (a) issue next chunk's QK mma first (latency hidden by PV below)
            if (kc < 3)
                QK_MMA(ks_base, 2 * (kc + 1), cn);
            // (b) PV stream for current chunk (independent of cn)
            PV_MMA(b_base, kc, A);
            // (c) EX2 + pack next chunk (QK results long ready)
            if (kc < 3)
                EXP_PACK(cn, A);
        }
        __syncthreads();          // compute done before buffer cur is restaged
    }

    // ---- exp-sum reduce across the quad (cols) and write ----
    l0 += __shfl_xor_sync(0xffffffffu, l0, 1);
    l0 += __shfl_xor_sync(0xffffffffu, l0, 2);
    l8 += __shfl_xor_sync(0xffffffffu, l8, 1);
    l8 += __shfl_xor_sync(0xffffffffu, l8, 2);
    const int qrow = qt * QBLK + w * 16 + g;
    if (tig == 0) {
        float* lp = &g_lP[(size_t)(s * BB + b) * NN];
        lp[qrow]     = l0;
        lp[qrow + 8] = l8;
    }

    // ---- write O partials (bf16) ----
    __nv_bfloat16* dstB = &g_accPh[(size_t)(s * BB + b) * NN * CC];
    const int c0 = 2 * tig;
#pragma unroll
    for (int nt = 0; nt < 8; ++nt) {
        const __nv_bfloat162 plo = __floats2bfloat162_rn(C[nt][0], C[nt][1]);
        const __nv_bfloat162 phi = __floats2bfloat162_rn(C[nt][2], C[nt][3]);
        *(__nv_bfloat162*)&dstB[(size_t)qrow * CC + nt * 8 + c0]       = plo;
        *(__nv_bfloat162*)&dstB[(size_t)(qrow + 8) * CC + nt * 8 + c0] = phi;
    }
#undef STAGE
#undef QK_MMA
#undef EXP_PACK
#undef PV_MMA

    // ---- election: last split block for this (qt,b) runs the combine ----
    __threadfence();
    __syncthreads();
    if (t == 0)
        s_last = atomicAdd(&g_cnt[b * NQT + qt], 1u);
    __syncthreads();
    if (s_last != NSPLIT - 1)
        return;
    __threadfence();

    // combine 128 queries x 64 ch, 256 threads: thread = (query, ch-half)
    {
        const int q    = t >> 1;
        const int half = (t & 1) * 32;
        const int n    = qt * QBLK + q;

        float l = 0.f;
#pragma unroll
        for (int ss = 0; ss < NSPLIT; ++ss)
            l += g_lP[(size_t)(ss * BB + b) * NN + n];
        const float inv = 1.0f / l;
        const float gm  = *gamma_p;

        const float* Xb = X   + (size_t)b * CC * NN + n;
        float*       Ob = out + (size_t)b * CC * NN + n;

#pragma unroll
        for (int i = 0; i < 4; ++i) {              // 4 chunks of 8 channels
            float a[8];
#pragma unroll
            for (int c = 0; c < 8; ++c) a[c] = 0.f;
#pragma unroll
            for (int ss = 0; ss < NSPLIT; ++ss) {
                const uint4 p = *(const uint4*)
                    &g_accPh[((size_t)(ss * BB + b) * NN + n) * CC + half + i * 8];
                const __nv_bfloat162* h = (const __nv_bfloat162*)&p;
#pragma unroll
                for (int j = 0; j < 4; ++j) {
                    const float2 f = __bfloat1622float2(h[j]);
                    a[2 * j]     += f.x;
                    a[2 * j + 1] += f.y;
                }
            }
#pragma unroll
            for (int c = 0; c < 8; ++c) {
                const int ch = half + i * 8 + c;
                Ob[(size_t)ch * NN] = fmaf(gm, a[c] * inv, Xb[(size_t)ch * NN]);
            }
        }
    }

    __syncthreads();
    if (t == 0)
        g_cnt[b * NQT + qt] = 0u;   // reset for graph replay
}

// ---------------------------------------------------------------------------
// Launch
// ---------------------------------------------------------------------------
extern "C" void kernel_launch(void* const* d_in, const int* in_sizes, int n_in,
                              void* d_out, int out_size)
{
    const float* X  = (const float*)d_in[0];
    const float* Wq = (const float*)d_in[1];
    const float* bq = (const float*)d_in[2];
    const float* Wk = (const float*)d_in[3];
    const float* bk = (const float*)d_in[4];
    const float* Wv = (const float*)d_in[5];
    const float* bv = (const float*)d_in[6];
    const float* gm = (const float*)d_in[7];
    float* out = (float*)d_out;

    dim3 g1(NN / 256, BB, 4);
    proj_kernel<<<g1, 256>>>(X, Wq, bq, Wk, bk, Wv, bv);

    dim3 g2(NQT, BB, NSPLIT);
    attn_partial<<<g2, 256>>>(X, gm, out);
}

// round 16
// speedup vs baseline: 1.0570x; 1.0570x over previous
#include <cuda_runtime.h>
#include <cuda_bf16.h>
#include <cstdint>

// Problem constants
#define BB 2
#define CC 64
#define NN 9216
#define CQD 8
#define NSPLIT 3
#define KEYS_PER_SPLIT (NN / NSPLIT)            // 3072
#define KT 64                                    // keys per tile
#define TILES_PER_SPLIT (KEYS_PER_SPLIT / KT)    // 48
#define QBLK 128
#define NQT (NN / QBLK)                          // 72
#define VP 72                                    // Vs row pitch in bf16 (144 B)
#define LOG2E 1.4426950408889634f
#define ONES_BF16X2 0x3F803F80u

// Scratch (device globals; no allocation allowed)
__device__ float g_Q[BB * NN * CQD];                         // tf32( q * log2e )
__device__ float g_K[BB * NN * CQD];                         // tf32, pair-PERMUTED
__device__ __align__(16) __nv_bfloat16 g_Vb[BB * NN * CC];   // bf16
__device__ __align__(16) __nv_bfloat16 g_accPh[NSPLIT * BB * NN * CC]; // partial O (bf16)
__device__ float g_lP[NSPLIT * BB * NN];                     // partial exp-sums
__device__ unsigned int g_cnt[BB * NQT];                     // split counters (0-init)

// ---------------------------------------------------------------------------
// PTX helpers
// ---------------------------------------------------------------------------
__device__ __forceinline__ uint32_t smem_u32(const void* p) {
    return (uint32_t)__cvta_generic_to_shared(p);
}

__device__ __forceinline__ void cp_async16(uint32_t dst, const void* src) {
    asm volatile("cp.async.cg.shared.global [%0], [%1], 16;" :: "r"(dst), "l"(src));
}
#define CP_COMMIT() asm volatile("cp.async.commit_group;")
#define CP_WAIT0()  asm volatile("cp.async.wait_group 0;")

__device__ __forceinline__ void ldmatrix_x4_trans(uint32_t& r0, uint32_t& r1,
                                                  uint32_t& r2, uint32_t& r3,
                                                  uint32_t addr) {
    asm volatile("ldmatrix.sync.aligned.m8n8.x4.trans.shared.b16 {%0,%1,%2,%3}, [%4];"
                 : "=r"(r0), "=r"(r1), "=r"(r2), "=r"(r3) : "r"(addr));
}

// bf16 PV mma: D(16x8) += A(16x16) * B(16x8)
__device__ __forceinline__ void mma16816(float& c0, float& c1, float& c2, float& c3,
                                         uint32_t a0, uint32_t a1, uint32_t a2, uint32_t a3,
                                         uint32_t b0, uint32_t b1) {
    asm volatile(
        "mma.sync.aligned.m16n8k16.row.col.f32.bf16.bf16.f32 "
        "{%0,%1,%2,%3}, {%4,%5,%6,%7}, {%8,%9}, {%0,%1,%2,%3};"
        : "+f"(c0), "+f"(c1), "+f"(c2), "+f"(c3)
        : "r"(a0), "r"(a1), "r"(a2), "r"(a3), "r"(b0), "r"(b1));
}

// tf32 QK mma: D(16x8) = A(16x8) * B(8x8)
__device__ __forceinline__ void mma_tf32(float& c0, float& c1, float& c2, float& c3,
                                         uint32_t a0, uint32_t a1, uint32_t a2, uint32_t a3,
                                         uint32_t b0, uint32_t b1) {
    asm volatile(
        "mma.sync.aligned.m16n8k8.row.col.f32.tf32.tf32.f32 "
        "{%0,%1,%2,%3}, {%4,%5,%6,%7}, {%8,%9}, {%0,%1,%2,%3};"
        : "+f"(c0), "+f"(c1), "+f"(c2), "+f"(c3)
        : "r"(a0), "r"(a1), "r"(a2), "r"(a3), "r"(b0), "r"(b1));
}

__device__ __forceinline__ float to_tf32(float x) {
    uint32_t y;
    asm("cvt.rna.tf32.f32 %0, %1;" : "=r"(y) : "f"(x));
    return __uint_as_float(y);
}

__device__ __forceinline__ float ex2(float x) {
    float y;
    asm("ex2.approx.f32 %0, %1;" : "=f"(y) : "f"(x));
    return y;
}

// ---------------------------------------------------------------------------
// Kernel 1: 1x1-conv projections (round-6 best-measured shape).
// grid (36, B, 4), 256 threads; z picks 20 of 80 outputs.
// K stored pair-PERMUTED: K'[2c]=K[c], K'[2c+1]=K[c+4] (c=0..3).
// ---------------------------------------------------------------------------
__global__ __launch_bounds__(256) void proj_kernel(
    const float* __restrict__ X,
    const float* __restrict__ Wq, const float* __restrict__ bq,
    const float* __restrict__ Wk, const float* __restrict__ bk,
    const float* __restrict__ Wv, const float* __restrict__ bv)
{
    __shared__ float Ws[20 * 64];
    __shared__ float bs[20];

    const int t = threadIdx.x;
    const int b = blockIdx.y;
    const int z = blockIdx.z;
    const int n = blockIdx.x * 256 + t;
    const int obase = z * 20;

    for (int i = t; i < 20 * 64; i += 256) {
        const int o = obase + (i >> 6), c = i & 63;
        Ws[i] = (o < 8) ? Wq[o * 64 + c]
              : (o < 16) ? Wk[(o - 8) * 64 + c]
                         : Wv[(o - 16) * 64 + c];
    }
    if (t < 20) {
        const int o = obase + t;
        bs[t] = (o < 8) ? bq[o] : (o < 16) ? bk[o - 8] : bv[o - 16];
    }

    float x[64];
    const float* Xb = X + (size_t)b * CC * NN + n;
#pragma unroll
    for (int c = 0; c < 64; ++c) x[c] = Xb[(size_t)c * NN];

    __syncthreads();

    float* qrow = &g_Q[(size_t)(b * NN + n) * CQD];
    float* krow = &g_K[(size_t)(b * NN + n) * CQD];
    __nv_bfloat16* vrow = &g_Vb[(size_t)(b * NN + n) * CC];

    const float4* Ws4 = (const float4*)Ws;
#pragma unroll 4
    for (int oo = 0; oo < 20; ++oo) {
        float a0 = bs[oo], a1 = 0.f, a2 = 0.f, a3 = 0.f;
#pragma unroll
        for (int c4 = 0; c4 < 16; c4 += 4) {
            const float4 w0 = Ws4[oo * 16 + c4 + 0];
            const float4 w1 = Ws4[oo * 16 + c4 + 1];
            const float4 w2 = Ws4[oo * 16 + c4 + 2];
            const float4 w3 = Ws4[oo * 16 + c4 + 3];
            a0 = fmaf(w0.x, x[4*c4+0],  a0); a0 = fmaf(w0.y, x[4*c4+1],  a0);
            a0 = fmaf(w0.z, x[4*c4+2],  a0); a0 = fmaf(w0.w, x[4*c4+3],  a0);
            a1 = fmaf(w1.x, x[4*c4+4],  a1); a1 = fmaf(w1.y, x[4*c4+5],  a1);
            a1 = fmaf(w1.z, x[4*c4+6],  a1); a1 = fmaf(w1.w, x[4*c4+7],  a1);
            a2 = fmaf(w2.x, x[4*c4+8],  a2); a2 = fmaf(w2.y, x[4*c4+9],  a2);
            a2 = fmaf(w2.z, x[4*c4+10], a2); a2 = fmaf(w2.w, x[4*c4+11], a2);
            a3 = fmaf(w3.x, x[4*c4+12], a3); a3 = fmaf(w3.y, x[4*c4+13], a3);
            a3 = fmaf(w3.z, x[4*c4+14], a3); a3 = fmaf(w3.w, x[4*c4+15], a3);
        }
        const float acc = (a0 + a1) + (a2 + a3);
        const int o = obase + oo;
        if (o < 8) {
            qrow[o] = to_tf32(acc * LOG2E);
        } else if (o < 16) {
            const int c = o - 8;
            const int idx = (c < 4) ? 2 * c : 2 * (c - 4) + 1;   // pair permutation
            krow[idx] = to_tf32(acc);
        } else {
            vrow[o - 16] = __float2bfloat16(acc);
        }
    }
}

// ---------------------------------------------------------------------------
// Kernel 2: partial attention + fused combine, software-pipelined chunks.
// grid (72, B, NSPLIT=3); 256 threads = 8 warps; warp owns 16 query rows.
// Round-14 base (l via ones-mma, QK-mma of chunk kc+1 issued before PV of
// chunk kc) + ONLY change: PV ldmatrix stream runs one step ahead of its
// consuming mma pair (single-variable experiment vs r14).
// ---------------------------------------------------------------------------
__global__ __launch_bounds__(256, 3) void attn_partial(
    const float* __restrict__ X,
    const float* __restrict__ gamma_p,
    float* __restrict__ out)
{
    __shared__ float Ks[2][KT * 8];                  // 2 x 2 KB
    __shared__ __nv_bfloat16 Vs[2][KT * VP];         // 2 x 9 KB
    __shared__ unsigned int s_last;

    const int t    = threadIdx.x;
    const int lane = t & 31;
    const int w    = t >> 5;
    const int b    = blockIdx.y;
    const int s    = blockIdx.z;
    const int qt   = blockIdx.x;
    const int g    = lane >> 2;
    const int tig  = lane & 3;

    // Q fragment (loop-invariant)
    const float* Qb = &g_Q[(size_t)(b * NN + qt * QBLK + w * 16) * CQD];
    const uint32_t qa0 = __float_as_uint(Qb[g * CQD + tig]);
    const uint32_t qa1 = __float_as_uint(Qb[(g + 8) * CQD + tig]);
    const uint32_t qa2 = __float_as_uint(Qb[g * CQD + tig + 4]);
    const uint32_t qa3 = __float_as_uint(Qb[(g + 8) * CQD + tig + 4]);

    float C[8][4], Cl[4];
#pragma unroll
    for (int i = 0; i < 8; ++i)
#pragma unroll
        for (int j = 0; j < 4; ++j) C[i][j] = 0.f;
#pragma unroll
    for (int j = 0; j < 4; ++j) Cl[j] = 0.f;

    const int kbase0 = s * KEYS_PER_SPLIT;
    const int vrow0  = t >> 3;            // 0..31
    const int vch    = (t & 7) * 8;       // bf16 col 0..56

    const uint32_t ks_u32[2] = { smem_u32(Ks[0]), smem_u32(Ks[1]) };
    const uint32_t vs_u32[2] = { smem_u32(Vs[0]), smem_u32(Vs[1]) };
    const uint32_t b_off = (lane & 15) * (VP * 2) + (lane >> 4) * 16;
    const uint32_t k_off = (uint32_t)(g * 32 + tig * 8);   // packed-pair byte offset

#define STAGE(TILE, BUF)                                                             \
    do {                                                                             \
        const size_t kb_ = (size_t)(b * NN + kbase0 + (TILE) * KT);                  \
        if (t < 128)                                                                 \
            cp_async16(ks_u32[BUF] + t * 16, (const char*)&g_K[kb_ * CQD] + t * 16); \
        cp_async16(vs_u32[BUF] + (vrow0 * VP + vch) * 2,                             \
                   &g_Vb[(kb_ + vrow0) * CC + vch]);                                 \
        cp_async16(vs_u32[BUF] + ((vrow0 + 32) * VP + vch) * 2,                      \
                   &g_Vb[(kb_ + vrow0 + 32) * CC + vch]);                            \
    } while (0)

    // QK (2 packed LDS.64 + 2 tf32 mma) for a 16-key chunk
#define QK_MMA(KSBASE, CT2, CN)                                                      \
    do {                                                                             \
        uint32_t kb0_, kb1_, kb2_, kb3_;                                             \
        asm volatile("ld.shared.v2.b32 {%0,%1}, [%2];"                               \
                     : "=r"(kb0_), "=r"(kb1_) : "r"((KSBASE) + (CT2) * 256));        \
        asm volatile("ld.shared.v2.b32 {%0,%1}, [%2];"                               \
                     : "=r"(kb2_), "=r"(kb3_) : "r"((KSBASE) + (CT2) * 256 + 256));  \
        (CN)[0] = 0.f; (CN)[1] = 0.f; (CN)[2] = 0.f; (CN)[3] = 0.f;                  \
        (CN)[4] = 0.f; (CN)[5] = 0.f; (CN)[6] = 0.f; (CN)[7] = 0.f;                  \
        mma_tf32((CN)[0], (CN)[1], (CN)[2], (CN)[3], qa0, qa1, qa2, qa3, kb0_, kb1_);\
        mma_tf32((CN)[4], (CN)[5], (CN)[6], (CN)[7], qa0, qa1, qa2, qa3, kb2_, kb3_);\
    } while (0)

    // EX2 + pack 8 logits into 4 A-frag words (no l chain here — l via ones-mma)
#define EXP_PACK(CN, A)                                                              \
    do {                                                                             \
        const __nv_bfloat162 p01_ = __floats2bfloat162_rn(ex2((CN)[0]), ex2((CN)[1]));\
        const __nv_bfloat162 p23_ = __floats2bfloat162_rn(ex2((CN)[2]), ex2((CN)[3]));\
        const __nv_bfloat162 p45_ = __floats2bfloat162_rn(ex2((CN)[4]), ex2((CN)[5]));\
        const __nv_bfloat162 p67_ = __floats2bfloat162_rn(ex2((CN)[6]), ex2((CN)[7]));\
        (A)[0] = *(const uint32_t*)&p01_;                                            \
        (A)[1] = *(const uint32_t*)&p23_;                                            \
        (A)[2] = *(const uint32_t*)&p45_;                                            \
        (A)[3] = *(const uint32_t*)&p67_;                                            \
    } while (0)

    // PV + l-mma for one chunk; ldmatrix stream one step ahead of its mma pair
#define PV_MMA(BBASE, KC, A)                                                         \
    do {                                                                             \
        const uint32_t pb_ = (BBASE) + (KC) * 16 * (VP * 2);                         \
        uint32_t b0_, b1_, b2_, b3_, c0_, c1_, c2_, c3_;                             \
        ldmatrix_x4_trans(b0_, b1_, b2_, b3_, pb_);                                  \
        mma16816(Cl[0], Cl[1], Cl[2], Cl[3],                                         \
                 (A)[0], (A)[1], (A)[2], (A)[3], ONES_BF16X2, ONES_BF16X2);          \
        ldmatrix_x4_trans(c0_, c1_, c2_, c3_, pb_ + 32);                             \
        mma16816(C[0][0], C[0][1], C[0][2], C[0][3],                                 \
                 (A)[0], (A)[1], (A)[2], (A)[3], b0_, b1_);                          \
        mma16816(C[1][0], C[1][1], C[1][2], C[1][3],                                 \
                 (A)[0], (A)[1], (A)[2], (A)[3], b2_, b3_);                          \
        ldmatrix_x4_trans(b0_, b1_, b2_, b3_, pb_ + 64);                             \
        mma16816(C[2][0], C[2][1], C[2][2], C[2][3],                                 \
                 (A)[0], (A)[1], (A)[2], (A)[3], c0_, c1_);                          \
        mma16816(C[3][0], C[3][1], C[3][2], C[3][3],                                 \
                 (A)[0], (A)[1], (A)[2], (A)[3], c2_, c3_);                          \
        ldmatrix_x4_trans(c0_, c1_, c2_, c3_, pb_ + 96);                             \
        mma16816(C[4][0], C[4][1], C[4][2], C[4][3],                                 \
                 (A)[0], (A)[1], (A)[2], (A)[3], b0_, b1_);                          \
        mma16816(C[5][0], C[5][1], C[5][2], C[5][3],                                 \
                 (A)[0], (A)[1], (A)[2], (A)[3], b2_, b3_);                          \
        mma16816(C[6][0], C[6][1], C[6][2], C[6][3],                                 \
                 (A)[0], (A)[1], (A)[2], (A)[3], c0_, c1_);                          \
        mma16816(C[7][0], C[7][1], C[7][2], C[7][3],                                 \
                 (A)[0], (A)[1], (A)[2], (A)[3], c2_, c3_);                          \
    } while (0)

    STAGE(0, 0);
    CP_COMMIT();

    for (int tile = 0; tile < TILES_PER_SPLIT; ++tile) {
        const int cur = tile & 1;

        CP_WAIT0();
        __syncthreads();          // buffer cur ready for all warps

        if (tile + 1 < TILES_PER_SPLIT) {
            STAGE(tile + 1, cur ^ 1);
            CP_COMMIT();
        }

        const uint32_t ks_base = ks_u32[cur] + k_off;
        const uint32_t b_base  = vs_u32[cur] + b_off;

        // pipeline prologue: A-frags for chunk 0
        float cn[8];
        uint32_t A[4];
        QK_MMA(ks_base, 0, cn);
        EXP_PACK(cn, A);

#pragma unroll
        for (int kc = 0; kc < 4; ++kc) {
            // (a) issue next chunk's QK mma first (latency hidden by PV below)
            if (kc < 3)
                QK_MMA(ks_base, 2 * (kc + 1), cn);
            // (b) PV stream for current chunk (independent of cn)
            PV_MMA(b_base, kc, A);
            // (c) EX2 + pack next chunk (QK results long ready)
            if (kc < 3)
                EXP_PACK(cn, A);
        }
        __syncthreads();          // compute done before buffer cur is restaged
    }

    // ---- write exp-sums (each quad lane holds the row sums via ones-mma) ----
    const int qrow = qt * QBLK + w * 16 + g;
    if (tig == 0) {
        float* lp = &g_lP[(size_t)(s * BB + b) * NN];
        lp[qrow]     = Cl[0];
        lp[qrow + 8] = Cl[2];
    }

    // ---- write O partials (bf16) ----
    __nv_bfloat16* dstB = &g_accPh[(size_t)(s * BB + b) * NN * CC];
    const int c0 = 2 * tig;
#pragma unroll
    for (int nt = 0; nt < 8; ++nt) {
        const __nv_bfloat162 plo = __floats2bfloat162_rn(C[nt][0], C[nt][1]);
        const __nv_bfloat162 phi = __floats2bfloat162_rn(C[nt][2], C[nt][3]);
        *(__nv_bfloat162*)&dstB[(size_t)qrow * CC + nt * 8 + c0]       = plo;
        *(__nv_bfloat162*)&dstB[(size_t)(qrow + 8) * CC + nt * 8 + c0] = phi;
    }
#undef STAGE
#undef QK_MMA
#undef EXP_PACK
#undef PV_MMA

    // ---- election: last split block for this (qt,b) runs the combine ----
    __threadfence();
    __syncthreads();
    if (t == 0)
        s_last = atomicAdd(&g_cnt[b * NQT + qt], 1u);
    __syncthreads();
    if (s_last != NSPLIT - 1)
        return;
    __threadfence();

    // combine 128 queries x 64 ch, 256 threads: thread = (query, ch-half)
    {
        const int q    = t >> 1;
        const int half = (t & 1) * 32;
        const int n    = qt * QBLK + q;

        float l = 0.f;
#pragma unroll
        for (int ss = 0; ss < NSPLIT; ++ss)
            l += g_lP[(size_t)(ss * BB + b) * NN + n];
        const float inv = 1.0f / l;
        const float gm  = *gamma_p;

        const float* Xb = X   + (size_t)b * CC * NN + n;
        float*       Ob = out + (size_t)b * CC * NN + n;

#pragma unroll
        for (int i = 0; i < 4; ++i) {              // 4 chunks of 8 channels
            float a[8];
#pragma unroll
            for (int c = 0; c < 8; ++c) a[c] = 0.f;
#pragma unroll
            for (int ss = 0; ss < NSPLIT; ++ss) {
                const uint4 p = *(const uint4*)
                    &g_accPh[((size_t)(ss * BB + b) * NN + n) * CC + half + i * 8];
                const __nv_bfloat162* h = (const __nv_bfloat162*)&p;
#pragma unroll
                for (int j = 0; j < 4; ++j) {
                    const float2 f = __bfloat1622float2(h[j]);
                    a[2 * j]     += f.x;
                    a[2 * j + 1] += f.y;
                }
            }
#pragma unroll
            for (int c = 0; c < 8; ++c) {
                const int ch = half + i * 8 + c;
                Ob[(size_t)ch * NN] = fmaf(gm, a[c] * inv, Xb[(size_t)ch * NN]);
            }
        }
    }

    __syncthreads();
    if (t == 0)
        g_cnt[b * NQT + qt] = 0u;   // reset for graph replay
}

// ---------------------------------------------------------------------------
// Launch
// ---------------------------------------------------------------------------
extern "C" void kernel_launch(void* const* d_in, const int* in_sizes, int n_in,
                              void* d_out, int out_size)
{
    const float* X  = (const float*)d_in[0];
    const float* Wq = (const float*)d_in[1];
    const float* bq = (const float*)d_in[2];
    const float* Wk = (const float*)d_in[3];
    const float* bk = (const float*)d_in[4];
    const float* Wv = (const float*)d_in[5];
    const float* bv = (const float*)d_in[6];
    const float* gm = (const float*)d_in[7];
    float* out = (float*)d_out;

    dim3 g1(NN / 256, BB, 4);
    proj_kernel<<<g1, 256>>>(X, Wq, bq, Wk, bk, Wv, bv);

    dim3 g2(NQT, BB, NSPLIT);
    attn_partial<<<g2, 256>>>(X, gm, out);
}